// round 7
// baseline (speedup 1.0000x reference)
#include <cuda_runtime.h>
#include <cuda_bf16.h>
#include <cstdint>

#define DEVFN __device__ __forceinline__
typedef int8_t i8;

// sm_103 (no 'a') toolchain: no tcgen05. Path: IMMA mma.sync s8 + cp.async.

// ---------------- problem dims ----------------
#define Bv   4
#define Nv   1024
#define Cv   1024
#define Hv   16
#define Dv   64
#define HIDv 4096
#define Tv   (Bv*Nv)
#define BH   (Bv*Hv)

// ---------------- quantizers ----------------
DEVFN float qz4(float x){ float r = rintf(x*16.0f);  r = fminf(fmaxf(r,-128.0f),127.0f); return r*0.0625f; }
DEVFN float qz7(float x){ float r = rintf(x*128.0f); r = fminf(fmaxf(r,-128.0f),127.0f); return r*0.0078125f; }
DEVFN int f2i8(float f){ int i = __float2int_rn(f); return max(-128, min(127, i)); }

// ---------------- device scratch (all int8 except x1) ----------------
__device__ __align__(128) i8  g_wqkv[3*Cv*Cv];      // rows: [q|k|v], int8 = w*128
__device__ __align__(128) i8  g_wpr [Cv*Cv];
__device__ __align__(128) i8  g_wf1 [HIDv*Cv];
__device__ __align__(128) i8  g_wf2 [Cv*HIDv];
__device__ __align__(128) i8  g_h1  [Tv*Cv];        // act int8 = a*16
__device__ __align__(128) i8  g_qb  [BH*Nv*Dv];
__device__ __align__(128) i8  g_kb  [BH*Nv*Dv];
__device__ __align__(128) i8  g_vt  [BH*Dv*Nv];     // V transposed: [bh][d][n]
__device__ __align__(128) i8  g_z2  [Tv*Cv];
__device__ __align__(128) float g_x1[Tv*Cv];
__device__ __align__(128) i8  g_h2  [Tv*Cv];
__device__ __align__(128) i8  g_m   [Tv*HIDv];

// ---------------- PTX helpers ----------------
DEVFN uint32_t s2u(const void* p){
    uint32_t a;
    asm("{ .reg .u64 t; cvta.to.shared.u64 t, %1; cvt.u32.u64 %0, t; }" : "=r"(a) : "l"(p));
    return a;
}
DEVFN void cpasync16(uint32_t d, const void* s){
    asm volatile("cp.async.cg.shared.global [%0], [%1], 16;" :: "r"(d), "l"(s));
}
DEVFN void cpcommit(){ asm volatile("cp.async.commit_group;" ::: "memory"); }
template<int N> DEVFN void cpwait(){ asm volatile("cp.async.wait_group %0;" :: "n"(N) : "memory"); }
DEVFN void ldsm4(uint32_t* r, uint32_t addr){
    asm volatile("ldmatrix.sync.aligned.m8n8.x4.shared.b16 {%0,%1,%2,%3}, [%4];"
        : "=r"(r[0]), "=r"(r[1]), "=r"(r[2]), "=r"(r[3]) : "r"(addr));
}
DEVFN void imma(int* c, const uint32_t* a, const uint32_t* b){
    asm volatile("mma.sync.aligned.m16n8k32.row.col.s32.s8.s8.s32 "
        "{%0,%1,%2,%3}, {%4,%5,%6,%7}, {%8,%9}, {%0,%1,%2,%3};"
        : "+r"(c[0]), "+r"(c[1]), "+r"(c[2]), "+r"(c[3])
        : "r"(a[0]), "r"(a[1]), "r"(a[2]), "r"(a[3]), "r"(b[0]), "r"(b[1]));
}
DEVFN void st_i8x2(i8* p, int a, int b){
    *reinterpret_cast<short*>(p) = (short)((a & 0xFF) | (b << 8));
}
// swizzle for 128-byte smem rows (c16 = 16B chunk 0..7)
DEVFN uint32_t swz(uint32_t r, uint32_t c16){ return (r<<7) + ((c16 ^ (r&7))<<4); }

// ---------------- epilogue functors (v already scaled to float by caller) ----------------
struct EpiQKV {
    i8* q; i8* k; i8* vt;
    DEVFN void operator()(int row, int col, float v0, float v1) const {
        int b=row>>10, n=row&1023;
        int sel=col>>10, rem=col&1023, h=rem>>6, d=rem&63;
        int i0 = f2i8(v0*16.0f), i1 = f2i8(v1*16.0f);
        if (sel==2){
            i8* dst = vt + ((long)(b*Hv+h)*Dv + d)*Nv + n;
            dst[0] = (i8)i0; dst[Nv] = (i8)i1;
        } else {
            i8* dst = (sel==0 ? q : k) + ((long)(b*Hv+h)*Nv + n)*Dv + d;
            st_i8x2(dst, i0, i1);
        }
    }
};
struct EpiProj {
    const float* x; const float* pb; const float* aw2; const float* ab2;
    float* x1; i8* h2;
    DEVFN void operator()(int row, int col, float v0, float v1) const {
        float a = qz4(aw2[0]), bb = qz4(ab2[0]);
        float2 xv = *(const float2*)(x + (long)row*Cv + col);
        float2 pv = *(const float2*)(pb + col);
        float y0 = v0 + qz7(pv.x),  y1 = v1 + qz7(pv.y);
        float o0 = qz4(xv.x) + qz4(y0), o1 = qz4(xv.y) + qz4(y1);
        *(float2*)(x1 + (long)row*Cv + col) = make_float2(o0, o1);
        float h0 = qz4(qz4(qz4(o0)*a) + bb);
        float h1 = qz4(qz4(qz4(o1)*a) + bb);
        st_i8x2(h2 + (long)row*Cv + col, f2i8(h0*16.0f), f2i8(h1*16.0f));
    }
};
struct EpiFc1 {
    const float* b1; i8* m;
    DEVFN void operator()(int row, int col, float v0, float v1) const {
        float2 bv = *(const float2*)(b1 + col);
        float y0 = fmaxf(v0 + qz7(bv.x), 0.f);
        float y1 = fmaxf(v1 + qz7(bv.y), 0.f);
        st_i8x2(m + (long)row*HIDv + col, f2i8(qz4(y0)*16.0f), f2i8(qz4(y1)*16.0f));
    }
};
struct EpiFc2 {
    const float* b2; const float* x1; float* out;
    DEVFN void operator()(int row, int col, float v0, float v1) const {
        float2 bv = *(const float2*)(b2 + col);
        float2 xv = *(const float2*)(x1 + (long)row*Cv + col);
        float y0 = v0 + qz7(bv.x), y1 = v1 + qz7(bv.y);
        *(float2*)(out + (long)row*Cv + col) =
            make_float2(qz4(xv.x) + qz4(y0), qz4(xv.y) + qz4(y1));
    }
};

// ---------------- int8 GEMM: C[128x128] = A @ B^T, BK=128 (bytes), 3-stage ----------------
constexpr int TILE = 128*128;        // 16 KB, 128B rows
constexpr int GSTG = 2*TILE;
constexpr int GSM  = 3*GSTG;         // 96 KB

template<class Epi>
__global__ void __launch_bounds__(256,2)
gemm_i8(const i8* __restrict__ A, const i8* __restrict__ Bm, int K, Epi epi)
{
    extern __shared__ char dsm[];
    uint32_t base = s2u(dsm);
    int tid = threadIdx.x, wid = tid>>5, lane = tid&31;
    int wm = wid & 3, wn = wid >> 2;
    int m0 = blockIdx.y*128, n0 = blockIdx.x*128;
    const i8* Ab = A + (long)m0*K;
    const i8* Bb = Bm + (long)n0*K;
    const int KC = K >> 7;

    auto load = [&](int ch, int st){
        uint32_t ab = base + st*GSTG, bb = ab + TILE;
        const i8* Ac = Ab + ch*128;
        const i8* Bc = Bb + ch*128;
        #pragma unroll
        for(int j=0;j<4;j++){
            int i = tid + j*256; int r = i>>3, c = i&7;
            cpasync16(ab + swz(r,c), Ac + (long)r*K + c*16);
            cpasync16(bb + swz(r,c), Bc + (long)r*K + c*16);
        }
        cpcommit();
    };

    int acc[2][8][4];
    #pragma unroll
    for(int im=0;im<2;im++)
        #pragma unroll
        for(int j=0;j<8;j++)
            #pragma unroll
            for(int u=0;u<4;u++) acc[im][j][u]=0;

    load(0,0);
    load(1,1);
    int t = lane>>3, lr = lane&7;
    int rAdd = (t&1)*8 + lr, cAdd16 = (t>>1);   // 16B-chunk offset

    for(int c=0;c<KC;c++){
        if (c+1 < KC) cpwait<1>(); else cpwait<0>();
        __syncthreads();
        if (c+2 < KC) load(c+2, (c+2)%3);
        uint32_t ab = base + (c%3)*GSTG, bb = ab + TILE;
        #pragma unroll
        for(int kw=0; kw<4; kw++){              // 4 x k32 windows per 128B chunk
            int ch = kw*2 + cAdd16;
            uint32_t afr[2][4];
            #pragma unroll
            for(int im=0;im<2;im++){
                int row = wm*32 + im*16 + rAdd;
                ldsm4(afr[im], ab + (row<<7) + ((ch ^ (row&7))<<4));
            }
            #pragma unroll
            for(int g=0; g<4; g++){
                int row = wn*64 + g*16 + rAdd;
                uint32_t r4[4];
                ldsm4(r4, bb + (row<<7) + ((ch ^ (row&7))<<4));
                uint32_t b0[2]={r4[0],r4[2]}, b1[2]={r4[1],r4[3]};
                #pragma unroll
                for(int im=0;im<2;im++){
                    imma(acc[im][2*g],   afr[im], b0);
                    imma(acc[im][2*g+1], afr[im], b1);
                }
            }
        }
    }

    const float SC = 1.0f/2048.0f;   // 2^-4 * 2^-7
    int row0 = m0 + wm*32 + (lane>>2);
    int col0 = n0 + wn*64 + (lane&3)*2;
    #pragma unroll
    for(int im=0;im<2;im++)
        #pragma unroll
        for(int j=0;j<8;j++){
            int r = row0 + im*16, cc = col0 + j*8;
            epi(r,   cc, (float)acc[im][j][0]*SC, (float)acc[im][j][1]*SC);
            epi(r+8, cc, (float)acc[im][j][2]*SC, (float)acc[im][j][3]*SC);
        }
}

// ---------------- fused attention (int8) ----------------
// S_int = Q_i . K_i  (scale 2^-8); logit qz4 index r = rn(S_int/128), clamp.
// Fixed softmax max M = 127/16 (logits clipped by qz4). exp LUT (256 entries).
// P int8 = clamp(rn(e * inv * 128)) in [0,127]; O_int = P_i . V_i, z = rn(O/128).
constexpr int QROW = 80;                         // padded 64B rows (16B-mult, ldsm conflict-free)
constexpr int QKSZ = 128*QROW;                   // 10240
constexpr int VSZ  = 64*128;                     // 8192, swizzled 128B rows
constexpr int FA_Q  = 1024;
constexpr int FA_K0 = FA_Q  + QKSZ;
constexpr int FA_K1 = FA_K0 + QKSZ;
constexpr int FA_V0 = FA_K1 + QKSZ;
constexpr int FA_V1 = FA_V0 + VSZ;
constexpr int FA_SM = FA_V1 + VSZ;               // 48128

__global__ void __launch_bounds__(256,2)
fattn_k(const i8* __restrict__ q, const i8* __restrict__ k,
        const i8* __restrict__ vt, i8* __restrict__ z2)
{
    extern __shared__ char dsm[];
    float* lut = (float*)dsm;
    uint32_t base = s2u(dsm);
    uint32_t qs = base + FA_Q;
    uint32_t ks[2] = {base+FA_K0, base+FA_K1};
    uint32_t vs[2] = {base+FA_V0, base+FA_V1};

    int tid = threadIdx.x, wid = tid>>5, lane = tid&31;
    int bh = blockIdx.y, b = bh>>4, h = bh&15;
    int q0 = blockIdx.x*128;
    const i8* Qb = q  + ((long)bh*Nv + q0)*Dv;
    const i8* Kb = k  + (long)bh*Nv*Dv;
    const i8* Vb = vt + (long)bh*Dv*Nv;

    lut[tid] = expf((float)(tid-128)*0.0625f - 7.9375f);

    #pragma unroll
    for(int j=0;j<2;j++){
        int i = tid + j*256; int r = i>>2, c = i&3;
        cpasync16(qs + r*QROW + c*16, Qb + (long)r*Dv + c*16);
    }
    cpcommit();

    int t = lane>>3, lr = lane&7;
    int rAdd = (t&1)*8 + lr, cAddB = (t>>1)*16;   // byte offset

    auto loadK = [&](int c, int st){
        const i8* src = Kb + (long)(c*128)*Dv;
        #pragma unroll
        for(int j=0;j<2;j++){
            int i = tid + j*256; int r = i>>2, cc = i&3;
            cpasync16(ks[st] + r*QROW + cc*16, src + (long)r*Dv + cc*16);
        }
        cpcommit();
    };
    auto loadKV = [&](int c, int st){
        const i8* sk = Kb + (long)(c*128)*Dv;
        const i8* sv = Vb + c*128;
        #pragma unroll
        for(int j=0;j<2;j++){
            int i = tid + j*256; int r = i>>2, cc = i&3;
            cpasync16(ks[st] + r*QROW + cc*16, sk + (long)r*Dv + cc*16);
        }
        #pragma unroll
        for(int j=0;j<2;j++){
            int i = tid + j*256; int r = i>>3, cc = i&7;
            cpasync16(vs[st] + swz(r,cc), sv + (long)r*Nv + cc*16);
        }
        cpcommit();
    };

    loadK(0, 0);
    cpwait<0>(); __syncthreads();

    uint32_t qf[2][4];                           // 2 k32 windows over D=64
    #pragma unroll
    for(int kw=0;kw<2;kw++){
        int row = wid*16 + rAdd;
        ldsm4(qf[kw], qs + row*QROW + kw*32 + cAddB);
    }

    auto computeS2 = [&](uint32_t kb_, int kg, int s2[2][4]){
        #pragma unroll
        for(int u=0;u<4;u++){ s2[0][u]=0; s2[1][u]=0; }
        #pragma unroll
        for(int kw=0;kw<2;kw++){
            int row = kg*16 + rAdd;
            uint32_t r4[4];
            ldsm4(r4, kb_ + row*QROW + kw*32 + cAddB);
            uint32_t b0[2]={r4[0],r4[2]}, b1[2]={r4[1],r4[3]};
            imma(s2[0], qf[kw], b0);
            imma(s2[1], qf[kw], b1);
        }
    };
    auto ev = [&](int s)->float{
        int idx = __float2int_rn((float)s * 0.0078125f);
        idx = max(-128, min(127, idx));
        return lut[idx + 128];
    };

    // ---- pass A: row sums of exp ----
    float rs0 = 0.f, rs1 = 0.f;
    for(int c=0;c<8;c++){
        cpwait<0>(); __syncthreads();
        if (c<7) loadK(c+1, (c+1)&1);
        #pragma unroll
        for(int kg=0;kg<8;kg++){
            int s2[2][4];
            computeS2(ks[c&1], kg, s2);
            rs0 += ev(s2[0][0]) + ev(s2[0][1]) + ev(s2[1][0]) + ev(s2[1][1]);
            rs1 += ev(s2[0][2]) + ev(s2[0][3]) + ev(s2[1][2]) + ev(s2[1][3]);
        }
    }
    rs0 += __shfl_xor_sync(0xffffffffu, rs0, 1);
    rs0 += __shfl_xor_sync(0xffffffffu, rs0, 2);
    rs1 += __shfl_xor_sync(0xffffffffu, rs1, 1);
    rs1 += __shfl_xor_sync(0xffffffffu, rs1, 2);
    float ps0 = 128.0f/rs0, ps1 = 128.0f/rs1;    // p_int = rn(e * 128*inv)

    auto pqv = [&](int s, float ps)->int{
        return min(__float2int_rn(ev(s) * ps), 127);
    };

    // ---- pass B: recompute S, pack P int8 a-frags via quad shfl, O += P@V ----
    int oacc[8][4];
    #pragma unroll
    for(int j=0;j<8;j++){ oacc[j][0]=0; oacc[j][1]=0; oacc[j][2]=0; oacc[j][3]=0; }

    int t3 = lane&3;
    int loSrc = (lane & 28) | ((2*t3)&3);
    int hiSrc = (lane & 28) | ((2*t3+1)&3);
    int sel = t3>>1;

    loadKV(0, 0);
    for(int c=0;c<8;c++){
        cpwait<0>(); __syncthreads();
        if (c<7) loadKV(c+1, (c+1)&1);
        #pragma unroll
        for(int w=0;w<4;w++){                    // 32-key windows
            int sA[2][4], sB[2][4];
            computeS2(ks[c&1], 2*w,   sA);
            computeS2(ks[c&1], 2*w+1, sB);
            uint32_t pkg[4];
            pkg[0] = (uint32_t)((pqv(sA[0][0],ps0)) | (pqv(sA[0][1],ps0)<<8) |
                                (pqv(sA[1][0],ps0)<<16) | (pqv(sA[1][1],ps0)<<24));
            pkg[1] = (uint32_t)((pqv(sA[0][2],ps1)) | (pqv(sA[0][3],ps1)<<8) |
                                (pqv(sA[1][2],ps1)<<16) | (pqv(sA[1][3],ps1)<<24));
            pkg[2] = (uint32_t)((pqv(sB[0][0],ps0)) | (pqv(sB[0][1],ps0)<<8) |
                                (pqv(sB[1][0],ps0)<<16) | (pqv(sB[1][1],ps0)<<24));
            pkg[3] = (uint32_t)((pqv(sB[0][2],ps1)) | (pqv(sB[0][3],ps1)<<8) |
                                (pqv(sB[1][2],ps1)<<16) | (pqv(sB[1][3],ps1)<<24));
            uint32_t afr[4];
            #pragma unroll
            for(int j=0;j<4;j++){
                uint32_t lo = __shfl_sync(0xffffffffu, pkg[j], loSrc);
                uint32_t hi = __shfl_sync(0xffffffffu, pkg[j], hiSrc);
                afr[j] = sel ? ((lo>>16) | (hi & 0xFFFF0000u))
                             : ((lo & 0xFFFFu) | (hi<<16));
            }
            #pragma unroll
            for(int dg=0;dg<4;dg++){
                int row = dg*16 + rAdd;
                int ch = w*2 + (t>>1);
                uint32_t r4[4];
                ldsm4(r4, vs[c&1] + (row<<7) + ((ch ^ (row&7))<<4));
                uint32_t b0[2]={r4[0],r4[2]}, b1[2]={r4[1],r4[3]};
                imma(oacc[2*dg],   afr, b0);
                imma(oacc[2*dg+1], afr, b1);
            }
        }
    }

    // z2 = qz4(O/2048) -> int8*16 = rn(O/128)
    int n = q0 + wid*16 + (lane>>2);
    long ro = ((long)(b*Nv) + n)*Cv + h*Dv;
    int d0 = 2*(lane&3);
    #pragma unroll
    for(int og=0;og<8;og++){
        st_i8x2(z2 + ro +        og*8 + d0,
                f2i8((float)oacc[og][0]*0.0078125f), f2i8((float)oacc[og][1]*0.0078125f));
        st_i8x2(z2 + ro + 8*Cv + og*8 + d0,
                f2i8((float)oacc[og][2]*0.0078125f), f2i8((float)oacc[og][3]*0.0078125f));
    }
}

// ---------------- elementwise kernels ----------------
__global__ void quantw_all(const float4* qw, const float4* kvw, const float4* pw,
                           const float4* f1w, const float4* f2w,
                           uint32_t* wqkv, uint32_t* wpr, uint32_t* wf1, uint32_t* wf2)
{
    int bx = blockIdx.x;
    const float4* src; uint32_t* dst; int li;
    if      (bx < 1024){ src=qw;  dst=wqkv;          li=bx; }
    else if (bx < 3072){ src=kvw; dst=wqkv + 262144; li=bx-1024; }
    else if (bx < 4096){ src=pw;  dst=wpr;           li=bx-3072; }
    else if (bx < 8192){ src=f1w; dst=wf1;           li=bx-4096; }
    else               { src=f2w; dst=wf2;           li=bx-8192; }
    int i = li*256 + threadIdx.x;
    float4 v = src[i];
    int a = f2i8(rintf(v.x*128.f)), b = f2i8(rintf(v.y*128.f));
    int c = f2i8(rintf(v.z*128.f)), d = f2i8(rintf(v.w*128.f));
    dst[i] = (uint32_t)((a&0xFF) | ((b&0xFF)<<8) | ((c&0xFF)<<16) | ((d&0xFF)<<24));
}
__global__ void affine4_k(const float4* __restrict__ x, const float* __restrict__ aw,
                          const float* __restrict__ ab, uint32_t* __restrict__ out, int n4){
    int i = blockIdx.x*blockDim.x + threadIdx.x;
    if(i<n4){
        float a = qz4(aw[0]), b = qz4(ab[0]);
        float4 v = x[i];
        float o[4] = {v.x,v.y,v.z,v.w};
        int q[4];
        #pragma unroll
        for(int u=0;u<4;u++){
            float tq = qz4(o[u])*a;
            q[u] = f2i8(qz4(qz4(tq)+b)*16.0f);
        }
        out[i] = (uint32_t)((q[0]&0xFF) | ((q[1]&0xFF)<<8) | ((q[2]&0xFF)<<16) | ((q[3]&0xFF)<<24));
    }
}

// ---------------- host launcher ----------------
extern "C" void kernel_launch(void* const* d_in, const int* in_sizes, int n_in,
                              void* d_out, int out_size)
{
    (void)in_sizes; (void)n_in; (void)out_size;
    const float* x   = (const float*)d_in[0];
    const float* qw  = (const float*)d_in[1];
    const float* kvw = (const float*)d_in[2];
    const float* pw  = (const float*)d_in[3];
    const float* pb  = (const float*)d_in[4];
    const float* f1w = (const float*)d_in[5];
    const float* f1b = (const float*)d_in[6];
    const float* f2w = (const float*)d_in[7];
    const float* f2b = (const float*)d_in[8];
    const float* a1w = (const float*)d_in[9];
    const float* a1b = (const float*)d_in[10];
    const float* a2w = (const float*)d_in[11];
    const float* a2b = (const float*)d_in[12];
    float* out = (float*)d_out;

    i8 *wqkv,*wpr,*wf1,*wf2,*h1,*qb,*kb,*vt,*z2,*h2,*m;
    float *x1;
    cudaGetSymbolAddress((void**)&wqkv,g_wqkv);
    cudaGetSymbolAddress((void**)&wpr, g_wpr);
    cudaGetSymbolAddress((void**)&wf1, g_wf1);
    cudaGetSymbolAddress((void**)&wf2, g_wf2);
    cudaGetSymbolAddress((void**)&h1,  g_h1);
    cudaGetSymbolAddress((void**)&qb,  g_qb);
    cudaGetSymbolAddress((void**)&kb,  g_kb);
    cudaGetSymbolAddress((void**)&vt,  g_vt);
    cudaGetSymbolAddress((void**)&z2,  g_z2);
    cudaGetSymbolAddress((void**)&x1,  g_x1);
    cudaGetSymbolAddress((void**)&h2,  g_h2);
    cudaGetSymbolAddress((void**)&m,   g_m);

    cudaFuncSetAttribute(gemm_i8<EpiQKV>, cudaFuncAttributeMaxDynamicSharedMemorySize, GSM);
    cudaFuncSetAttribute(gemm_i8<EpiProj>,cudaFuncAttributeMaxDynamicSharedMemorySize, GSM);
    cudaFuncSetAttribute(gemm_i8<EpiFc1>, cudaFuncAttributeMaxDynamicSharedMemorySize, GSM);
    cudaFuncSetAttribute(gemm_i8<EpiFc2>, cudaFuncAttributeMaxDynamicSharedMemorySize, GSM);
    cudaFuncSetAttribute(fattn_k,         cudaFuncAttributeMaxDynamicSharedMemorySize, FA_SM);

    // 1) quantize all weights -> int8 (w*128)
    quantw_all<<<12288, 256>>>((const float4*)qw, (const float4*)kvw, (const float4*)pw,
                               (const float4*)f1w, (const float4*)f2w,
                               (uint32_t*)wqkv, (uint32_t*)wpr, (uint32_t*)wf1, (uint32_t*)wf2);

    // 2) affine1 + quant -> h1 int8 (a*16)
    affine4_k<<<(Tv*Cv/4+255)/256, 256>>>((const float4*)x, a1w, a1b, (uint32_t*)h1, Tv*Cv/4);

    // 3) fused qkv projection (writes q,k + V transposed)
    { EpiQKV e{qb,kb,vt};
      gemm_i8<EpiQKV><<<dim3(3*Cv/128, Tv/128), 256, GSM>>>(h1, wqkv, Cv, e); }

    // 4) fused attention -> z2 int8
    fattn_k<<<dim3(Nv/128, BH), 256, FA_SM>>>(qb, kb, vt, z2);

    // 5) proj + add1 + affine2 -> x1 f32, h2 int8
    { EpiProj e{x, pb, a2w, a2b, x1, h2};
      gemm_i8<EpiProj><<<dim3(Cv/128,  Tv/128), 256, GSM>>>(z2, wpr, Cv, e); }
    // 6) fc1 + relu -> m int8
    { EpiFc1 e{f1b, m};
      gemm_i8<EpiFc1><<<dim3(HIDv/128, Tv/128), 256, GSM>>>(h2, wf1, Cv, e); }
    // 7) fc2 + add2 -> out f32
    { EpiFc2 e{f2b, x1, out};
      gemm_i8<EpiFc2><<<dim3(Cv/128,  Tv/128), 256, GSM>>>(m, wf2, HIDv, e); }
}

// round 8
// speedup vs baseline: 1.7688x; 1.7688x over previous
#include <cuda_runtime.h>
#include <cuda_bf16.h>
#include <cstdint>

typedef __nv_bfloat16 bf16;
#define DEVFN __device__ __forceinline__

// sm_103 (no 'a') toolchain: no tcgen05; bf16 mma.sync (HMMA) + cp.async path.
// R7 lesson: s8 IMMA is a slow path on this target — bf16 HMMA only.

// ---------------- problem dims ----------------
#define Bv   4
#define Nv   1024
#define Cv   1024
#define Hv   16
#define Dv   64
#define HIDv 4096
#define Tv   (Bv*Nv)
#define BH   (Bv*Hv)

// ---------------- quantizers ----------------
DEVFN float qz4(float x){ float r = rintf(x*16.0f);  r = fminf(fmaxf(r,-128.0f),127.0f); return r*0.0625f; }
DEVFN float qz7(float x){ float r = rintf(x*128.0f); r = fminf(fmaxf(r,-128.0f),127.0f); return r*0.0078125f; }

// ---------------- device scratch ----------------
__device__ __align__(128) bf16 g_wqkv[3*Cv*Cv];
__device__ __align__(128) bf16 g_wpr [Cv*Cv];
__device__ __align__(128) bf16 g_wf1 [HIDv*Cv];
__device__ __align__(128) bf16 g_wf2 [Cv*HIDv];
__device__ __align__(128) bf16 g_h1  [Tv*Cv];
__device__ __align__(128) bf16 g_qb  [BH*Nv*Dv];
__device__ __align__(128) bf16 g_kb  [BH*Nv*Dv];
__device__ __align__(128) bf16 g_vb  [BH*Nv*Dv];
__device__ __align__(128) bf16 g_z2  [Tv*Cv];
__device__ __align__(128) float g_x1 [Tv*Cv];
__device__ __align__(128) bf16 g_h2  [Tv*Cv];
__device__ __align__(128) bf16 g_m   [Tv*HIDv];

// ---------------- PTX helpers ----------------
DEVFN uint32_t s2u(const void* p){
    uint32_t a;
    asm("{ .reg .u64 t; cvta.to.shared.u64 t, %1; cvt.u32.u64 %0, t; }" : "=r"(a) : "l"(p));
    return a;
}
DEVFN void cpasync16(uint32_t d, const void* s){
    asm volatile("cp.async.cg.shared.global [%0], [%1], 16;" :: "r"(d), "l"(s));
}
DEVFN void cpcommit(){ asm volatile("cp.async.commit_group;" ::: "memory"); }
template<int N> DEVFN void cpwait(){ asm volatile("cp.async.wait_group %0;" :: "n"(N) : "memory"); }
DEVFN void ldsm4(uint32_t* r, uint32_t addr){
    asm volatile("ldmatrix.sync.aligned.m8n8.x4.shared.b16 {%0,%1,%2,%3}, [%4];"
        : "=r"(r[0]), "=r"(r[1]), "=r"(r[2]), "=r"(r[3]) : "r"(addr));
}
DEVFN void ldsm4t(uint32_t* r, uint32_t addr){
    asm volatile("ldmatrix.sync.aligned.m8n8.x4.trans.shared.b16 {%0,%1,%2,%3}, [%4];"
        : "=r"(r[0]), "=r"(r[1]), "=r"(r[2]), "=r"(r[3]) : "r"(addr));
}
DEVFN void mma16816(float* c, const uint32_t* a, const uint32_t* b){
    asm volatile("mma.sync.aligned.m16n8k16.row.col.f32.bf16.bf16.f32 "
        "{%0,%1,%2,%3}, {%4,%5,%6,%7}, {%8,%9}, {%0,%1,%2,%3};"
        : "+f"(c[0]), "+f"(c[1]), "+f"(c[2]), "+f"(c[3])
        : "r"(a[0]), "r"(a[1]), "r"(a[2]), "r"(a[3]), "r"(b[0]), "r"(b[1]));
}
DEVFN void st_bf2(bf16* p, float a, float b){
    __nv_bfloat162 t = __halves2bfloat162(__float2bfloat16(a), __float2bfloat16(b));
    *reinterpret_cast<__nv_bfloat162*>(p) = t;
}
DEVFN uint32_t swz(uint32_t r, uint32_t c16){ return (r<<7) + ((c16 ^ (r&7))<<4); }

// ---------------- epilogue functors ----------------
struct EpiQKV {
    bf16* q; bf16* k; bf16* v;
    DEVFN void operator()(int row, int col, float v0, float v1) const {
        int b=row>>10, n=row&1023;
        int sel=col>>10, rem=col&1023, h=rem>>6, d=rem&63;
        bf16* dst = (sel==0 ? q : (sel==1 ? k : v)) + (((long)(b*Hv+h))*Nv + n)*Dv + d;
        st_bf2(dst, qz4(v0), qz4(v1));
    }
};
struct EpiProj {
    const float* x; const float* pb; const float* aw2; const float* ab2;
    float* x1; bf16* h2;
    DEVFN void operator()(int row, int col, float v0, float v1) const {
        float a = qz4(aw2[0]), bb = qz4(ab2[0]);
        float2 xv = *(const float2*)(x + (long)row*Cv + col);
        float2 pv = *(const float2*)(pb + col);
        float y0 = v0 + qz7(pv.x),  y1 = v1 + qz7(pv.y);
        float o0 = qz4(xv.x) + qz4(y0), o1 = qz4(xv.y) + qz4(y1);
        *(float2*)(x1 + (long)row*Cv + col) = make_float2(o0, o1);
        float h0 = qz4(qz4(qz4(o0)*a) + bb);
        float h1 = qz4(qz4(qz4(o1)*a) + bb);
        st_bf2(h2 + (long)row*Cv + col, h0, h1);
    }
};
struct EpiFc1 {
    const float* b1; bf16* m;
    DEVFN void operator()(int row, int col, float v0, float v1) const {
        float2 bv = *(const float2*)(b1 + col);
        float y0 = fmaxf(v0 + qz7(bv.x), 0.f);
        float y1 = fmaxf(v1 + qz7(bv.y), 0.f);
        st_bf2(m + (long)row*HIDv + col, qz4(y0), qz4(y1));
    }
};
struct EpiFc2 {
    const float* b2; const float* x1; float* out;
    DEVFN void operator()(int row, int col, float v0, float v1) const {
        float2 bv = *(const float2*)(b2 + col);
        float2 xv = *(const float2*)(x1 + (long)row*Cv + col);
        float y0 = v0 + qz7(bv.x), y1 = v1 + qz7(bv.y);
        *(float2*)(out + (long)row*Cv + col) =
            make_float2(qz4(xv.x) + qz4(y0), qz4(xv.y) + qz4(y1));
    }
};

// ---------------- GEMM: C[128x256] = A @ B^T, warp tile 64x64, BK=64, 3-stage ----------------
constexpr int ATILE = 128*128;       // 16 KB (128 rows x 128 B)
constexpr int BTILE = 256*128;       // 32 KB
constexpr int GSTG  = ATILE + BTILE; // 48 KB
constexpr int GSM   = 3*GSTG;        // 144 KB

template<class Epi>
__global__ void __launch_bounds__(256,1)
gemm_mma(const bf16* __restrict__ A, const bf16* __restrict__ Bm, int K, Epi epi)
{
    extern __shared__ char dsm[];
    uint32_t base = s2u(dsm);
    int tid = threadIdx.x, wid = tid>>5, lane = tid&31;
    int wm = wid & 1, wn = wid >> 1;          // 2 x 4 warps, each 64x64
    int m0 = blockIdx.y*128, n0 = blockIdx.x*256;
    const bf16* Ab = A + (long)m0*K;
    const bf16* Bb = Bm + (long)n0*K;
    const int KC = K >> 6;

    auto load = [&](int ch, int st){
        uint32_t ab = base + st*GSTG, bb = ab + ATILE;
        const bf16* Ac = Ab + ch*64;
        const bf16* Bc = Bb + ch*64;
        #pragma unroll
        for(int j=0;j<4;j++){
            int i = tid + j*256; int r = i>>3, c = i&7;
            cpasync16(ab + swz(r,c), Ac + (long)r*K + c*8);
        }
        #pragma unroll
        for(int j=0;j<8;j++){
            int i = tid + j*256; int r = i>>3, c = i&7;
            cpasync16(bb + swz(r,c), Bc + (long)r*K + c*8);
        }
        cpcommit();
    };

    float acc[4][8][4];
    #pragma unroll
    for(int mb=0;mb<4;mb++)
        #pragma unroll
        for(int j=0;j<8;j++)
            #pragma unroll
            for(int u=0;u<4;u++) acc[mb][j][u]=0.f;

    load(0,0);
    load(1,1);
    int t = lane>>3, lr = lane&7;
    int rAdd = (t&1)*8 + lr, cAdd = (t>>1)*8;

    for(int c=0;c<KC;c++){
        if (c+1 < KC) cpwait<1>(); else cpwait<0>();
        __syncthreads();
        if (c+2 < KC) load(c+2, (c+2)%3);
        uint32_t ab = base + (c%3)*GSTG, bb = ab + ATILE;
        #pragma unroll
        for(int kk=0; kk<64; kk+=16){
            int ch = (kk + cAdd)>>3;
            uint32_t afr[4][4];
            #pragma unroll
            for(int mb=0;mb<4;mb++){
                int row = wm*64 + mb*16 + rAdd;
                ldsm4(afr[mb], ab + (row<<7) + ((ch ^ (row&7))<<4));
            }
            #pragma unroll
            for(int g=0; g<4; g++){
                int row = wn*64 + g*16 + rAdd;
                uint32_t r4[4];
                ldsm4(r4, bb + (row<<7) + ((ch ^ (row&7))<<4));
                uint32_t b0[2]={r4[0],r4[2]}, b1[2]={r4[1],r4[3]};
                #pragma unroll
                for(int mb=0;mb<4;mb++){
                    mma16816(acc[mb][2*g],   afr[mb], b0);
                    mma16816(acc[mb][2*g+1], afr[mb], b1);
                }
            }
        }
    }

    int colB = n0 + wn*64 + (lane&3)*2;
    #pragma unroll
    for(int mb=0;mb<4;mb++){
        int row0 = m0 + wm*64 + mb*16 + (lane>>2);
        #pragma unroll
        for(int j=0;j<8;j++){
            int cc = colB + j*8;
            epi(row0,   cc, acc[mb][j][0], acc[mb][j][1]);
            epi(row0+8, cc, acc[mb][j][2], acc[mb][j][3]);
        }
    }
}

// ---------------- fused attention: 4 warps x 32 query rows, 128 thr, 2 CTAs/SM ----------------
constexpr int TILE = 128*128;               // 16 KB K/V/Q tiles
constexpr int FA_Q  = 1024;                 // after 256-float LUT
constexpr int FA_K0 = FA_Q  + TILE;
constexpr int FA_K1 = FA_K0 + TILE;
constexpr int FA_V0 = FA_K1 + TILE;
constexpr int FA_V1 = FA_V0 + TILE;
constexpr int FA_SM = FA_V1 + TILE;         // 82944

__global__ void __launch_bounds__(128,2)
fattn_k(const bf16* __restrict__ q, const bf16* __restrict__ k,
        const bf16* __restrict__ v, bf16* __restrict__ z2)
{
    extern __shared__ char dsm[];
    float* lut = (float*)dsm;
    uint32_t base = s2u(dsm);
    uint32_t qs = base + FA_Q;
    uint32_t ks[2] = {base+FA_K0, base+FA_K1};
    uint32_t vs[2] = {base+FA_V0, base+FA_V1};

    int tid = threadIdx.x, wid = tid>>5, lane = tid&31;
    int bh = blockIdx.y, b = bh>>4, h = bh&15;
    int q0 = blockIdx.x*128;
    const bf16* Qb = q + ((long)bh*Nv + q0)*Dv;
    const bf16* Kb = k + (long)bh*Nv*Dv;
    const bf16* Vb = v + (long)bh*Nv*Dv;

    lut[tid]     = expf((float)(tid-128)*0.0625f - 7.9375f);
    lut[tid+128] = expf((float)(tid)*0.0625f - 7.9375f);

    #pragma unroll
    for(int j=0;j<8;j++){
        int i = tid + j*128; int r = i>>3, c = i&7;
        cpasync16(qs + swz(r,c), Qb + (long)r*Dv + c*8);
    }
    cpcommit();

    int t = lane>>3, lr = lane&7;
    int rAdd = (t&1)*8 + lr, cAdd = (t>>1)*8;

    auto loadK = [&](int c, int st){
        const bf16* src = Kb + (long)(c*128)*Dv;
        #pragma unroll
        for(int j=0;j<8;j++){
            int i = tid + j*128; int r = i>>3, cc = i&7;
            cpasync16(ks[st] + swz(r,cc), src + (long)r*Dv + cc*8);
        }
        cpcommit();
    };
    auto loadKV = [&](int c, int st){
        const bf16* sk = Kb + (long)(c*128)*Dv;
        const bf16* sv = Vb + (long)(c*128)*Dv;
        #pragma unroll
        for(int j=0;j<8;j++){
            int i = tid + j*128; int r = i>>3, cc = i&7;
            cpasync16(ks[st] + swz(r,cc), sk + (long)r*Dv + cc*8);
            cpasync16(vs[st] + swz(r,cc), sv + (long)r*Dv + cc*8);
        }
        cpcommit();
    };

    loadK(0, 0);
    cpwait<0>(); __syncthreads();

    uint32_t qf[2][4][4];                        // [mblock][kk]
    #pragma unroll
    for(int mb=0;mb<2;mb++)
        #pragma unroll
        for(int kk=0;kk<4;kk++){
            int row = wid*32 + mb*16 + rAdd;
            int ch = (kk*16 + cAdd)>>3;
            ldsm4(qf[mb][kk], qs + (row<<7) + ((ch ^ (row&7))<<4));
        }

    // S for one 16-key group, both query m-blocks: s2[mb][nb][4]
    auto computeS2 = [&](uint32_t kb_, int kg, float s2[2][2][4]){
        #pragma unroll
        for(int mb=0;mb<2;mb++)
            #pragma unroll
            for(int u=0;u<4;u++){ s2[mb][0][u]=0.f; s2[mb][1][u]=0.f; }
        #pragma unroll
        for(int kk=0;kk<4;kk++){
            int row = kg*16 + rAdd;
            int ch = (kk*16 + cAdd)>>3;
            uint32_t r4[4];
            ldsm4(r4, kb_ + (row<<7) + ((ch ^ (row&7))<<4));
            uint32_t b0[2]={r4[0],r4[2]}, b1[2]={r4[1],r4[3]};
            #pragma unroll
            for(int mb=0;mb<2;mb++){
                mma16816(s2[mb][0], qf[mb][kk], b0);
                mma16816(s2[mb][1], qf[mb][kk], b1);
            }
        }
    };
    auto lutv = [&](float s)->float{
        float r = rintf(s*2.0f);
        r = fminf(fmaxf(r,-128.f),127.f);
        return lut[(int)r + 128];
    };

    // ---- pass A: row sums ----
    float rs[2][2] = {{0.f,0.f},{0.f,0.f}};
    for(int c=0;c<8;c++){
        cpwait<0>(); __syncthreads();
        if (c<7) loadK(c+1, (c+1)&1);
        #pragma unroll
        for(int kg=0;kg<8;kg++){
            float s2[2][2][4];
            computeS2(ks[c&1], kg, s2);
            #pragma unroll
            for(int mb=0;mb<2;mb++){
                rs[mb][0] += lutv(s2[mb][0][0]) + lutv(s2[mb][0][1]) + lutv(s2[mb][1][0]) + lutv(s2[mb][1][1]);
                rs[mb][1] += lutv(s2[mb][0][2]) + lutv(s2[mb][0][3]) + lutv(s2[mb][1][2]) + lutv(s2[mb][1][3]);
            }
        }
    }
    float inv[2][2];
    #pragma unroll
    for(int mb=0;mb<2;mb++)
        #pragma unroll
        for(int hh=0;hh<2;hh++){
            float r = rs[mb][hh];
            r += __shfl_xor_sync(0xffffffffu, r, 1);
            r += __shfl_xor_sync(0xffffffffu, r, 2);
            inv[mb][hh] = 1.0f/r;
        }

    auto pq = [&](float s, float iv)->uint32_t{
        float p = lutv(s)*iv;
        float r = rintf(p*128.f);
        r = fminf(fmaxf(r,-128.f),127.f);
        bf16 bv = __float2bfloat16(r*0.0078125f);
        return (uint32_t)*reinterpret_cast<uint16_t*>(&bv);
    };

    // ---- pass B: recompute S, O += P @ V ----
    float oacc[2][8][4];
    #pragma unroll
    for(int mb=0;mb<2;mb++)
        #pragma unroll
        for(int j=0;j<8;j++){ oacc[mb][j][0]=0.f; oacc[mb][j][1]=0.f; oacc[mb][j][2]=0.f; oacc[mb][j][3]=0.f; }

    loadKV(0, 0);
    for(int c=0;c<8;c++){
        cpwait<0>(); __syncthreads();
        if (c<7) loadKV(c+1, (c+1)&1);
        #pragma unroll
        for(int kg=0;kg<8;kg++){
            float s2[2][2][4];
            computeS2(ks[c&1], kg, s2);
            uint32_t pa[2][4];
            #pragma unroll
            for(int mb=0;mb<2;mb++){
                pa[mb][0] = pq(s2[mb][0][0],inv[mb][0]) | (pq(s2[mb][0][1],inv[mb][0])<<16);
                pa[mb][1] = pq(s2[mb][0][2],inv[mb][1]) | (pq(s2[mb][0][3],inv[mb][1])<<16);
                pa[mb][2] = pq(s2[mb][1][0],inv[mb][0]) | (pq(s2[mb][1][1],inv[mb][0])<<16);
                pa[mb][3] = pq(s2[mb][1][2],inv[mb][1]) | (pq(s2[mb][1][3],inv[mb][1])<<16);
            }
            #pragma unroll
            for(int dg=0;dg<4;dg++){
                int row = kg*16 + rAdd;
                int ch = (dg*16 + cAdd)>>3;
                uint32_t r4[4];
                ldsm4t(r4, vs[c&1] + (row<<7) + ((ch ^ (row&7))<<4));
                uint32_t b0[2]={r4[0],r4[1]}, b1[2]={r4[2],r4[3]};
                #pragma unroll
                for(int mb=0;mb<2;mb++){
                    mma16816(oacc[mb][2*dg],   pa[mb], b0);
                    mma16816(oacc[mb][2*dg+1], pa[mb], b1);
                }
            }
        }
    }

    int d0 = 2*(lane&3);
    #pragma unroll
    for(int mb=0;mb<2;mb++){
        int n = q0 + wid*32 + mb*16 + (lane>>2);
        long ro = ((long)(b*Nv) + n)*Cv + h*Dv;
        #pragma unroll
        for(int og=0;og<8;og++){
            st_bf2(z2 + ro +        og*8 + d0, qz4(oacc[mb][og][0]), qz4(oacc[mb][og][1]));
            st_bf2(z2 + ro + 8*Cv + og*8 + d0, qz4(oacc[mb][og][2]), qz4(oacc[mb][og][3]));
        }
    }
}

// ---------------- elementwise kernels ----------------
__global__ void quantw_all(const float4* qw, const float4* kvw, const float4* pw,
                           const float4* f1w, const float4* f2w,
                           uint2* wqkv, uint2* wpr, uint2* wf1, uint2* wf2)
{
    int bx = blockIdx.x;
    const float4* src; uint2* dst; int li;
    if      (bx < 1024){ src=qw;  dst=wqkv;          li=bx; }
    else if (bx < 3072){ src=kvw; dst=wqkv + 262144; li=bx-1024; }
    else if (bx < 4096){ src=pw;  dst=wpr;           li=bx-3072; }
    else if (bx < 8192){ src=f1w; dst=wf1;           li=bx-4096; }
    else               { src=f2w; dst=wf2;           li=bx-8192; }
    int i = li*256 + threadIdx.x;
    float4 v = src[i];
    __nv_bfloat162 lo = __halves2bfloat162(__float2bfloat16(qz7(v.x)), __float2bfloat16(qz7(v.y)));
    __nv_bfloat162 hi = __halves2bfloat162(__float2bfloat16(qz7(v.z)), __float2bfloat16(qz7(v.w)));
    dst[i] = make_uint2(*(uint32_t*)&lo, *(uint32_t*)&hi);
}
__global__ void affine4_k(const float4* __restrict__ x, const float* __restrict__ aw,
                          const float* __restrict__ ab, uint2* __restrict__ out, int n4){
    int i = blockIdx.x*blockDim.x + threadIdx.x;
    if(i<n4){
        float a = qz4(aw[0]), b = qz4(ab[0]);
        float4 v = x[i];
        float o[4] = {v.x,v.y,v.z,v.w};
        #pragma unroll
        for(int u=0;u<4;u++){ float t = qz4(o[u])*a; o[u] = qz4(qz4(t)+b); }
        __nv_bfloat162 lo = __halves2bfloat162(__float2bfloat16(o[0]), __float2bfloat16(o[1]));
        __nv_bfloat162 hi = __halves2bfloat162(__float2bfloat16(o[2]), __float2bfloat16(o[3]));
        out[i] = make_uint2(*(uint32_t*)&lo, *(uint32_t*)&hi);
    }
}

// ---------------- host launcher ----------------
extern "C" void kernel_launch(void* const* d_in, const int* in_sizes, int n_in,
                              void* d_out, int out_size)
{
    (void)in_sizes; (void)n_in; (void)out_size;
    const float* x   = (const float*)d_in[0];
    const float* qw  = (const float*)d_in[1];
    const float* kvw = (const float*)d_in[2];
    const float* pw  = (const float*)d_in[3];
    const float* pb  = (const float*)d_in[4];
    const float* f1w = (const float*)d_in[5];
    const float* f1b = (const float*)d_in[6];
    const float* f2w = (const float*)d_in[7];
    const float* f2b = (const float*)d_in[8];
    const float* a1w = (const float*)d_in[9];
    const float* a1b = (const float*)d_in[10];
    const float* a2w = (const float*)d_in[11];
    const float* a2b = (const float*)d_in[12];
    float* out = (float*)d_out;

    bf16 *wqkv,*wpr,*wf1,*wf2,*h1,*qb,*kb,*vb,*z2,*h2,*m;
    float *x1;
    cudaGetSymbolAddress((void**)&wqkv,g_wqkv);
    cudaGetSymbolAddress((void**)&wpr, g_wpr);
    cudaGetSymbolAddress((void**)&wf1, g_wf1);
    cudaGetSymbolAddress((void**)&wf2, g_wf2);
    cudaGetSymbolAddress((void**)&h1,  g_h1);
    cudaGetSymbolAddress((void**)&qb,  g_qb);
    cudaGetSymbolAddress((void**)&kb,  g_kb);
    cudaGetSymbolAddress((void**)&vb,  g_vb);
    cudaGetSymbolAddress((void**)&z2,  g_z2);
    cudaGetSymbolAddress((void**)&x1,  g_x1);
    cudaGetSymbolAddress((void**)&h2,  g_h2);
    cudaGetSymbolAddress((void**)&m,   g_m);

    cudaFuncSetAttribute(gemm_mma<EpiQKV>, cudaFuncAttributeMaxDynamicSharedMemorySize, GSM);
    cudaFuncSetAttribute(gemm_mma<EpiProj>,cudaFuncAttributeMaxDynamicSharedMemorySize, GSM);
    cudaFuncSetAttribute(gemm_mma<EpiFc1>, cudaFuncAttributeMaxDynamicSharedMemorySize, GSM);
    cudaFuncSetAttribute(gemm_mma<EpiFc2>, cudaFuncAttributeMaxDynamicSharedMemorySize, GSM);
    cudaFuncSetAttribute(fattn_k,          cudaFuncAttributeMaxDynamicSharedMemorySize, FA_SM);

    // 1) quantize all weights
    quantw_all<<<12288, 256>>>((const float4*)qw, (const float4*)kvw, (const float4*)pw,
                               (const float4*)f1w, (const float4*)f2w,
                               (uint2*)wqkv, (uint2*)wpr, (uint2*)wf1, (uint2*)wf2);

    // 2) affine1 + input quant
    affine4_k<<<(Tv*Cv/4+255)/256, 256>>>((const float4*)x, a1w, a1b, (uint2*)h1, Tv*Cv/4);

    // 3) fused qkv projection
    { EpiQKV e{qb,kb,vb};
      gemm_mma<EpiQKV><<<dim3(3*Cv/256, Tv/128), 256, GSM>>>(h1, wqkv, Cv, e); }

    // 4) fused attention -> z2
    fattn_k<<<dim3(Nv/128, BH), 128, FA_SM>>>(qb, kb, vb, z2);

    // 5) proj + add1 + affine2
    { EpiProj e{x, pb, a2w, a2b, x1, h2};
      gemm_mma<EpiProj><<<dim3(Cv/256,  Tv/128), 256, GSM>>>(z2, wpr, Cv, e); }
    // 6) fc1 + relu
    { EpiFc1 e{f1b, m};
      gemm_mma<EpiFc1><<<dim3(HIDv/256, Tv/128), 256, GSM>>>(h2, wf1, Cv, e); }
    // 7) fc2 + add2 -> out
    { EpiFc2 e{f2b, x1, out};
      gemm_mma<EpiFc2><<<dim3(Cv/256,  Tv/128), 256, GSM>>>(m, wf2, HIDv, e); }
}

// round 10
// speedup vs baseline: 2.0480x; 1.1578x over previous
#include <cuda_runtime.h>
#include <cuda_bf16.h>
#include <cstdint>

typedef __nv_bfloat16 bf16;
#define DEVFN __device__ __forceinline__

// sm_103 (no 'a') toolchain: no tcgen05; bf16 mma.sync (HMMA) + cp.async path.
// R7: s8 IMMA is slow on this target. R8: fattn is work-limited, not occupancy-limited.

// ---------------- problem dims ----------------
#define Bv   4
#define Nv   1024
#define Cv   1024
#define Hv   16
#define Dv   64
#define HIDv 4096
#define Tv   (Bv*Nv)
#define BH   (Bv*Hv)

// ---------------- quantizers ----------------
DEVFN float qz4(float x){ float r = rintf(x*16.0f);  r = fminf(fmaxf(r,-128.0f),127.0f); return r*0.0625f; }
DEVFN float qz7(float x){ float r = rintf(x*128.0f); r = fminf(fmaxf(r,-128.0f),127.0f); return r*0.0078125f; }

// ---------------- device scratch ----------------
__device__ __align__(128) bf16 g_wqkv[3*Cv*Cv];
__device__ __align__(128) bf16 g_wpr [Cv*Cv];
__device__ __align__(128) bf16 g_wf1 [HIDv*Cv];
__device__ __align__(128) bf16 g_wf2 [Cv*HIDv];
__device__ __align__(128) bf16 g_h1  [Tv*Cv];
__device__ __align__(128) bf16 g_qb  [BH*Nv*Dv];
__device__ __align__(128) bf16 g_kb  [BH*Nv*Dv];
__device__ __align__(128) bf16 g_vb  [BH*Nv*Dv];
__device__ __align__(128) bf16 g_z2  [Tv*Cv];
__device__ __align__(128) float g_x1 [Tv*Cv];
__device__ __align__(128) bf16 g_h2  [Tv*Cv];
__device__ __align__(128) bf16 g_m   [Tv*HIDv];

// ---------------- PTX helpers ----------------
DEVFN uint32_t s2u(const void* p){
    uint32_t a;
    asm("{ .reg .u64 t; cvta.to.shared.u64 t, %1; cvt.u32.u64 %0, t; }" : "=r"(a) : "l"(p));
    return a;
}
DEVFN void cpasync16(uint32_t d, const void* s){
    asm volatile("cp.async.cg.shared.global [%0], [%1], 16;" :: "r"(d), "l"(s));
}
DEVFN void cpcommit(){ asm volatile("cp.async.commit_group;" ::: "memory"); }
template<int N> DEVFN void cpwait(){ asm volatile("cp.async.wait_group %0;" :: "n"(N) : "memory"); }
DEVFN void ldsm4(uint32_t* r, uint32_t addr){
    asm volatile("ldmatrix.sync.aligned.m8n8.x4.shared.b16 {%0,%1,%2,%3}, [%4];"
        : "=r"(r[0]), "=r"(r[1]), "=r"(r[2]), "=r"(r[3]) : "r"(addr));
}
DEVFN void ldsm4t(uint32_t* r, uint32_t addr){
    asm volatile("ldmatrix.sync.aligned.m8n8.x4.trans.shared.b16 {%0,%1,%2,%3}, [%4];"
        : "=r"(r[0]), "=r"(r[1]), "=r"(r[2]), "=r"(r[3]) : "r"(addr));
}
DEVFN void mma16816(float* c, const uint32_t* a, const uint32_t* b){
    asm volatile("mma.sync.aligned.m16n8k16.row.col.f32.bf16.bf16.f32 "
        "{%0,%1,%2,%3}, {%4,%5,%6,%7}, {%8,%9}, {%0,%1,%2,%3};"
        : "+f"(c[0]), "+f"(c[1]), "+f"(c[2]), "+f"(c[3])
        : "r"(a[0]), "r"(a[1]), "r"(a[2]), "r"(a[3]), "r"(b[0]), "r"(b[1]));
}
DEVFN void st_bf2(bf16* p, float a, float b){
    __nv_bfloat162 t = __halves2bfloat162(__float2bfloat16(a), __float2bfloat16(b));
    *reinterpret_cast<__nv_bfloat162*>(p) = t;
}
DEVFN void sts64(uint32_t addr, uint32_t a, uint32_t b){
    asm volatile("st.shared.v2.u32 [%0], {%1,%2};" :: "r"(addr), "r"(a), "r"(b) : "memory");
}
DEVFN void lds64(uint32_t addr, uint32_t& a, uint32_t& b){
    asm volatile("ld.shared.v2.u32 {%0,%1}, [%2];" : "=r"(a), "=r"(b) : "r"(addr));
}
DEVFN uint32_t swz(uint32_t r, uint32_t c16){ return (r<<7) + ((c16 ^ (r&7))<<4); }

// ---------------- epilogue functors ----------------
struct EpiQKV {
    bf16* q; bf16* k; bf16* v;
    DEVFN void operator()(int row, int col, float v0, float v1) const {
        int b=row>>10, n=row&1023;
        int sel=col>>10, rem=col&1023, h=rem>>6, d=rem&63;
        bf16* dst = (sel==0 ? q : (sel==1 ? k : v)) + (((long)(b*Hv+h))*Nv + n)*Dv + d;
        st_bf2(dst, qz4(v0), qz4(v1));
    }
};
struct EpiProj {
    const float* x; const float* pb; const float* aw2; const float* ab2;
    float* x1; bf16* h2;
    DEVFN void operator()(int row, int col, float v0, float v1) const {
        float a = qz4(aw2[0]), bb = qz4(ab2[0]);
        float2 xv = *(const float2*)(x + (long)row*Cv + col);
        float2 pv = *(const float2*)(pb + col);
        float y0 = v0 + qz7(pv.x),  y1 = v1 + qz7(pv.y);
        float o0 = qz4(xv.x) + qz4(y0), o1 = qz4(xv.y) + qz4(y1);
        *(float2*)(x1 + (long)row*Cv + col) = make_float2(o0, o1);
        float h0 = qz4(qz4(qz4(o0)*a) + bb);
        float h1 = qz4(qz4(qz4(o1)*a) + bb);
        st_bf2(h2 + (long)row*Cv + col, h0, h1);
    }
};
struct EpiFc1 {
    const float* b1; bf16* m;
    DEVFN void operator()(int row, int col, float v0, float v1) const {
        float2 bv = *(const float2*)(b1 + col);
        float y0 = fmaxf(v0 + qz7(bv.x), 0.f);
        float y1 = fmaxf(v1 + qz7(bv.y), 0.f);
        st_bf2(m + (long)row*HIDv + col, qz4(y0), qz4(y1));
    }
};
struct EpiFc2 {
    const float* b2; const float* x1; float* out;
    DEVFN void operator()(int row, int col, float v0, float v1) const {
        float2 bv = *(const float2*)(b2 + col);
        float2 xv = *(const float2*)(x1 + (long)row*Cv + col);
        float y0 = v0 + qz7(bv.x), y1 = v1 + qz7(bv.y);
        *(float2*)(out + (long)row*Cv + col) =
            make_float2(qz4(xv.x) + qz4(y0), qz4(xv.y) + qz4(y1));
    }
};

// ---------------- GEMM: C[128x128] = A @ B^T, BK=64, 3-stage, swizzled (R6) ----------------
constexpr int TILE = 128*128;        // 16 KB (128 rows x 128 B)
constexpr int GSTG = 2*TILE;         // A + B stage = 32 KB
constexpr int GSM  = 3*GSTG;         // 96 KB

template<class Epi>
__global__ void __launch_bounds__(256,2)
gemm_mma(const bf16* __restrict__ A, const bf16* __restrict__ Bm, int K, Epi epi)
{
    extern __shared__ char dsm[];
    uint32_t base = s2u(dsm);
    int tid = threadIdx.x, wid = tid>>5, lane = tid&31;
    int wm = wid & 3, wn = wid >> 2;
    int m0 = blockIdx.y*128, n0 = blockIdx.x*128;
    const bf16* Ab = A + (long)m0*K;
    const bf16* Bb = Bm + (long)n0*K;
    const int KC = K >> 6;

    auto load = [&](int ch, int st){
        uint32_t ab = base + st*GSTG, bb = ab + TILE;
        const bf16* Ac = Ab + ch*64;
        const bf16* Bc = Bb + ch*64;
        #pragma unroll
        for(int j=0;j<4;j++){
            int i = tid + j*256; int r = i>>3, c = i&7;
            cpasync16(ab + swz(r,c), Ac + (long)r*K + c*8);
            cpasync16(bb + swz(r,c), Bc + (long)r*K + c*8);
        }
        cpcommit();
    };

    float acc[2][8][4];
    #pragma unroll
    for(int im=0;im<2;im++)
        #pragma unroll
        for(int j=0;j<8;j++)
            #pragma unroll
            for(int u=0;u<4;u++) acc[im][j][u]=0.f;

    load(0,0);
    load(1,1);
    int t = lane>>3, lr = lane&7;
    int rAdd = (t&1)*8 + lr, cAdd = (t>>1)*8;

    for(int c=0;c<KC;c++){
        if (c+1 < KC) cpwait<1>(); else cpwait<0>();
        __syncthreads();
        if (c+2 < KC) load(c+2, (c+2)%3);
        uint32_t ab = base + (c%3)*GSTG, bb = ab + TILE;
        #pragma unroll
        for(int kk=0; kk<64; kk+=16){
            int ch = (kk + cAdd)>>3;
            uint32_t afr[2][4];
            #pragma unroll
            for(int im=0;im<2;im++){
                int row = wm*32 + im*16 + rAdd;
                ldsm4(afr[im], ab + (row<<7) + ((ch ^ (row&7))<<4));
            }
            #pragma unroll
            for(int g=0; g<4; g++){
                int row = wn*64 + g*16 + rAdd;
                uint32_t r4[4];
                ldsm4(r4, bb + (row<<7) + ((ch ^ (row&7))<<4));
                uint32_t b0[2]={r4[0],r4[2]}, b1[2]={r4[1],r4[3]};
                #pragma unroll
                for(int im=0;im<2;im++){
                    mma16816(acc[im][2*g],   afr[im], b0);
                    mma16816(acc[im][2*g+1], afr[im], b1);
                }
            }
        }
    }

    int row0 = m0 + wm*32 + (lane>>2);
    int col0 = n0 + wn*64 + (lane&3)*2;
    #pragma unroll
    for(int im=0;im<2;im++)
        #pragma unroll
        for(int j=0;j<8;j++){
            int r = row0 + im*16, cc = col0 + j*8;
            epi(r,   cc, acc[im][j][0], acc[im][j][1]);
            epi(r+8, cc, acc[im][j][2], acc[im][j][3]);
        }
}

// ---------------- fused attention: pass A stores logit-index bytes; pass B has no S recompute ----
// smem: [LUT 1K][Q 16K][IDX 128K][KV0 16K][KV1 16K] = 177 KB, 1 CTA/SM, 256 thr (8 warps x 16 rows)
constexpr int FA_Q   = 1024;
constexpr int FA_IDX = FA_Q + TILE;           // 17408, 128KB: [chunk][warp][kg][lane] x 8B
constexpr int FA_KV0 = FA_IDX + 131072;       // 148480
constexpr int FA_KV1 = FA_KV0 + TILE;         // 164864
constexpr int FA_SM  = FA_KV1 + TILE;         // 181248

__global__ void __launch_bounds__(256,1)
fattn_k(const bf16* __restrict__ q, const bf16* __restrict__ k,
        const bf16* __restrict__ v, bf16* __restrict__ z2)
{
    extern __shared__ char dsm[];
    float* lut = (float*)dsm;
    uint32_t base = s2u(dsm);
    uint32_t qs = base + FA_Q;
    uint32_t idxb = base + FA_IDX;
    uint32_t kv[2] = {base+FA_KV0, base+FA_KV1};

    int tid = threadIdx.x, wid = tid>>5, lane = tid&31;
    int bh = blockIdx.y, b = bh>>4, h = bh&15;
    int q0 = blockIdx.x*128;
    const bf16* Qb = q + ((long)bh*Nv + q0)*Dv;
    const bf16* Kb = k + (long)bh*Nv*Dv;
    const bf16* Vb = v + (long)bh*Nv*Dv;

    lut[tid] = expf((float)(tid-128)*0.0625f - 7.9375f);

    #pragma unroll
    for(int j=0;j<4;j++){
        int i = tid + j*256; int r = i>>3, c = i&7;
        cpasync16(qs + swz(r,c), Qb + (long)r*Dv + c*8);
    }
    cpcommit();

    int t = lane>>3, lr = lane&7;
    int rAdd = (t&1)*8 + lr, cAdd = (t>>1)*8;

    auto loadT = [&](const bf16* src, int st){
        #pragma unroll
        for(int j=0;j<4;j++){
            int i = tid + j*256; int r = i>>3, cc = i&7;
            cpasync16(kv[st] + swz(r,cc), src + (long)r*Dv + cc*8);
        }
        cpcommit();
    };

    loadT(Kb, 0);
    cpwait<0>(); __syncthreads();

    uint32_t qf[4][4];
    #pragma unroll
    for(int kk=0;kk<4;kk++){
        int row = wid*16 + rAdd;
        int ch = (kk*16 + cAdd)>>3;
        ldsm4(qf[kk], qs + (row<<7) + ((ch ^ (row&7))<<4));
    }

    auto computeS2 = [&](uint32_t kb_, int kg, float s2[2][4]){
        #pragma unroll
        for(int u=0;u<4;u++){ s2[0][u]=0.f; s2[1][u]=0.f; }
        #pragma unroll
        for(int kk=0;kk<4;kk++){
            int row = kg*16 + rAdd;
            int ch = (kk*16 + cAdd)>>3;
            uint32_t r4[4];
            ldsm4(r4, kb_ + (row<<7) + ((ch ^ (row&7))<<4));
            uint32_t b0[2]={r4[0],r4[2]}, b1[2]={r4[1],r4[3]};
            mma16816(s2[0], qf[kk], b0);
            mma16816(s2[1], qf[kk], b1);
        }
    };
    auto idxq = [&](float s)->uint32_t{
        float r = rintf(s*2.0f);
        r = fminf(fmaxf(r,-128.f),127.f);
        return (uint32_t)((int)r + 128);
    };

    // ---- pass A: S once, store index bytes (fragment order), row sums ----
    float rs0 = 0.f, rs1 = 0.f;
    for(int c=0;c<8;c++){
        cpwait<0>(); __syncthreads();
        if (c<7) loadT(Kb + (long)((c+1)*128)*Dv, (c+1)&1);
        #pragma unroll
        for(int kg=0;kg<8;kg++){
            float s2[2][4];
            computeS2(kv[c&1], kg, s2);
            uint32_t i00=idxq(s2[0][0]), i01=idxq(s2[0][1]), i02=idxq(s2[0][2]), i03=idxq(s2[0][3]);
            uint32_t i10=idxq(s2[1][0]), i11=idxq(s2[1][1]), i12=idxq(s2[1][2]), i13=idxq(s2[1][3]);
            rs0 += lut[i00] + lut[i01] + lut[i10] + lut[i11];
            rs1 += lut[i02] + lut[i03] + lut[i12] + lut[i13];
            uint32_t w0 = i00 | (i01<<8) | (i10<<16) | (i11<<24);
            uint32_t w1 = i02 | (i03<<8) | (i12<<16) | (i13<<24);
            sts64(idxb + (uint32_t)(((c*8 + wid)*8 + kg)*32 + lane)*8, w0, w1);
        }
    }
    rs0 += __shfl_xor_sync(0xffffffffu, rs0, 1);
    rs0 += __shfl_xor_sync(0xffffffffu, rs0, 2);
    rs1 += __shfl_xor_sync(0xffffffffu, rs1, 1);
    rs1 += __shfl_xor_sync(0xffffffffu, rs1, 2);
    float inv0 = 1.0f/rs0, inv1 = 1.0f/rs1;

    auto pqb = [&](uint32_t byte, float iv)->uint32_t{
        float p = lut[byte]*iv;
        float r = rintf(p*128.f);
        r = fminf(fmaxf(r,-128.f),127.f);
        bf16 bv = __float2bfloat16(r*0.0078125f);
        return (uint32_t)*reinterpret_cast<uint16_t*>(&bv);
    };

    // ---- pass B: P from stored bytes, O += P @ V (no K reads, no S mma) ----
    float oacc[8][4];
    #pragma unroll
    for(int j=0;j<8;j++){ oacc[j][0]=0.f; oacc[j][1]=0.f; oacc[j][2]=0.f; oacc[j][3]=0.f; }

    loadT(Vb, 0);     // buffer 0 free (last K chunk used buffer 1)
    for(int c=0;c<8;c++){
        cpwait<0>(); __syncthreads();
        if (c<7) loadT(Vb + (long)((c+1)*128)*Dv, (c+1)&1);
        #pragma unroll
        for(int kg=0;kg<8;kg++){
            uint32_t w0, w1;
            lds64(idxb + (uint32_t)(((c*8 + wid)*8 + kg)*32 + lane)*8, w0, w1);
            uint32_t pa[4];
            pa[0] = pqb(w0&255u, inv0)      | (pqb((w0>>8)&255u, inv0)<<16);
            pa[1] = pqb(w1&255u, inv1)      | (pqb((w1>>8)&255u, inv1)<<16);
            pa[2] = pqb((w0>>16)&255u,inv0) | (pqb(w0>>24, inv0)<<16);
            pa[3] = pqb((w1>>16)&255u,inv1) | (pqb(w1>>24, inv1)<<16);
            #pragma unroll
            for(int dg=0;dg<4;dg++){
                int row = kg*16 + rAdd;
                int ch = (dg*16 + cAdd)>>3;
                uint32_t r4[4];
                ldsm4t(r4, kv[c&1] + (row<<7) + ((ch ^ (row&7))<<4));
                uint32_t b0[2]={r4[0],r4[1]}, b1[2]={r4[2],r4[3]};
                mma16816(oacc[2*dg],   pa, b0);
                mma16816(oacc[2*dg+1], pa, b1);
            }
        }
    }

    int n = q0 + wid*16 + (lane>>2);
    long ro = ((long)(b*Nv) + n)*Cv + h*Dv;
    int d0 = 2*(lane&3);
    #pragma unroll
    for(int og=0;og<8;og++){
        st_bf2(z2 + ro +        og*8 + d0, qz4(oacc[og][0]), qz4(oacc[og][1]));
        st_bf2(z2 + ro + 8*Cv + og*8 + d0, qz4(oacc[og][2]), qz4(oacc[og][3]));
    }
}

// ---------------- elementwise kernels ----------------
__global__ void quantw_all(const float4* qw, const float4* kvw, const float4* pw,
                           const float4* f1w, const float4* f2w,
                           uint2* wqkv, uint2* wpr, uint2* wf1, uint2* wf2)
{
    int bx = blockIdx.x;
    const float4* src; uint2* dst; int li;
    if      (bx < 1024){ src=qw;  dst=wqkv;          li=bx; }
    else if (bx < 3072){ src=kvw; dst=wqkv + 262144; li=bx-1024; }
    else if (bx < 4096){ src=pw;  dst=wpr;           li=bx-3072; }
    else if (bx < 8192){ src=f1w; dst=wf1;           li=bx-4096; }
    else               { src=f2w; dst=wf2;           li=bx-8192; }
    int i = li*256 + threadIdx.x;
    float4 v = src[i];
    __nv_bfloat162 lo = __halves2bfloat162(__float2bfloat16(qz7(v.x)), __float2bfloat16(qz7(v.y)));
    __nv_bfloat162 hi = __halves2bfloat162(__float2bfloat16(qz7(v.z)), __float2bfloat16(qz7(v.w)));
    dst[i] = make_uint2(*(uint32_t*)&lo, *(uint32_t*)&hi);
}
__global__ void affine4_k(const float4* __restrict__ x, const float* __restrict__ aw,
                          const float* __restrict__ ab, uint2* __restrict__ out, int n4){
    int i = blockIdx.x*blockDim.x + threadIdx.x;
    if(i<n4){
        float a = qz4(aw[0]), b = qz4(ab[0]);
        float4 v = x[i];
        float o[4] = {v.x,v.y,v.z,v.w};
        #pragma unroll
        for(int u=0;u<4;u++){ float t = qz4(o[u])*a; o[u] = qz4(qz4(t)+b); }
        __nv_bfloat162 lo = __halves2bfloat162(__float2bfloat16(o[0]), __float2bfloat16(o[1]));
        __nv_bfloat162 hi = __halves2bfloat162(__float2bfloat16(o[2]), __float2bfloat16(o[3]));
        out[i] = make_uint2(*(uint32_t*)&lo, *(uint32_t*)&hi);
    }
}

// ---------------- host launcher ----------------
extern "C" void kernel_launch(void* const* d_in, const int* in_sizes, int n_in,
                              void* d_out, int out_size)
{
    (void)in_sizes; (void)n_in; (void)out_size;
    const float* x   = (const float*)d_in[0];
    const float* qw  = (const float*)d_in[1];
    const float* kvw = (const float*)d_in[2];
    const float* pw  = (const float*)d_in[3];
    const float* pb  = (const float*)d_in[4];
    const float* f1w = (const float*)d_in[5];
    const float* f1b = (const float*)d_in[6];
    const float* f2w = (const float*)d_in[7];
    const float* f2b = (const float*)d_in[8];
    const float* a1w = (const float*)d_in[9];
    const float* a1b = (const float*)d_in[10];
    const float* a2w = (const float*)d_in[11];
    const float* a2b = (const float*)d_in[12];
    float* out = (float*)d_out;

    bf16 *wqkv,*wpr,*wf1,*wf2,*h1,*qb,*kb,*vb,*z2,*h2,*m;
    float *x1;
    cudaGetSymbolAddress((void**)&wqkv,g_wqkv);
    cudaGetSymbolAddress((void**)&wpr, g_wpr);
    cudaGetSymbolAddress((void**)&wf1, g_wf1);
    cudaGetSymbolAddress((void**)&wf2, g_wf2);
    cudaGetSymbolAddress((void**)&h1,  g_h1);
    cudaGetSymbolAddress((void**)&qb,  g_qb);
    cudaGetSymbolAddress((void**)&kb,  g_kb);
    cudaGetSymbolAddress((void**)&vb,  g_vb);
    cudaGetSymbolAddress((void**)&z2,  g_z2);
    cudaGetSymbolAddress((void**)&x1,  g_x1);
    cudaGetSymbolAddress((void**)&h2,  g_h2);
    cudaGetSymbolAddress((void**)&m,   g_m);

    cudaFuncSetAttribute(gemm_mma<EpiQKV>, cudaFuncAttributeMaxDynamicSharedMemorySize, GSM);
    cudaFuncSetAttribute(gemm_mma<EpiProj>,cudaFuncAttributeMaxDynamicSharedMemorySize, GSM);
    cudaFuncSetAttribute(gemm_mma<EpiFc1>, cudaFuncAttributeMaxDynamicSharedMemorySize, GSM);
    cudaFuncSetAttribute(gemm_mma<EpiFc2>, cudaFuncAttributeMaxDynamicSharedMemorySize, GSM);
    cudaFuncSetAttribute(fattn_k,          cudaFuncAttributeMaxDynamicSharedMemorySize, FA_SM);

    // 1) quantize all weights
    quantw_all<<<12288, 256>>>((const float4*)qw, (const float4*)kvw, (const float4*)pw,
                               (const float4*)f1w, (const float4*)f2w,
                               (uint2*)wqkv, (uint2*)wpr, (uint2*)wf1, (uint2*)wf2);

    // 2) affine1 + input quant
    affine4_k<<<(Tv*Cv/4+255)/256, 256>>>((const float4*)x, a1w, a1b, (uint2*)h1, Tv*Cv/4);

    // 3) fused qkv projection
    { EpiQKV e{qb,kb,vb};
      gemm_mma<EpiQKV><<<dim3(3*Cv/128, Tv/128), 256, GSM>>>(h1, wqkv, Cv, e); }

    // 4) fused attention -> z2
    fattn_k<<<dim3(Nv/128, BH), 256, FA_SM>>>(qb, kb, vb, z2);

    // 5) proj + add1 + affine2
    { EpiProj e{x, pb, a2w, a2b, x1, h2};
      gemm_mma<EpiProj><<<dim3(Cv/128,  Tv/128), 256, GSM>>>(z2, wpr, Cv, e); }
    // 6) fc1 + relu
    { EpiFc1 e{f1b, m};
      gemm_mma<EpiFc1><<<dim3(HIDv/128, Tv/128), 256, GSM>>>(h2, wf1, Cv, e); }
    // 7) fc2 + add2 -> out
    { EpiFc2 e{f2b, x1, out};
      gemm_mma<EpiFc2><<<dim3(Cv/128,  Tv/128), 256, GSM>>>(m, wf2, HIDv, e); }
}

// round 11
// speedup vs baseline: 2.2951x; 1.1206x over previous
#include <cuda_runtime.h>
#include <cuda_bf16.h>
#include <cstdint>

typedef __nv_bfloat16 bf16;
#define DEVFN __device__ __forceinline__

// sm_103 (no 'a') toolchain: no tcgen05; bf16 mma.sync (HMMA) + cp.async path.
// R7: s8 IMMA slow. R8: fattn work-limited. R9/R10: fattn scalar+LDS-conflict bound.

// ---------------- problem dims ----------------
#define Bv   4
#define Nv   1024
#define Cv   1024
#define Hv   16
#define Dv   64
#define HIDv 4096
#define Tv   (Bv*Nv)
#define BH   (Bv*Hv)

// ---------------- quantizers ----------------
DEVFN float qz4(float x){ float r = rintf(x*16.0f);  r = fminf(fmaxf(r,-128.0f),127.0f); return r*0.0625f; }
DEVFN float qz7(float x){ float r = rintf(x*128.0f); r = fminf(fmaxf(r,-128.0f),127.0f); return r*0.0078125f; }

// ---------------- device scratch ----------------
__device__ __align__(128) bf16 g_wqkv[3*Cv*Cv];
__device__ __align__(128) bf16 g_wpr [Cv*Cv];
__device__ __align__(128) bf16 g_wf1 [HIDv*Cv];
__device__ __align__(128) bf16 g_wf2 [Cv*HIDv];
__device__ __align__(128) bf16 g_h1  [Tv*Cv];
__device__ __align__(128) bf16 g_qb  [BH*Nv*Dv];     // Q pre-scaled x2 (exact)
__device__ __align__(128) bf16 g_kb  [BH*Nv*Dv];
__device__ __align__(128) bf16 g_vb  [BH*Nv*Dv];
__device__ __align__(128) bf16 g_z2  [Tv*Cv];
__device__ __align__(128) float g_x1 [Tv*Cv];
__device__ __align__(128) bf16 g_h2  [Tv*Cv];
__device__ __align__(128) bf16 g_m   [Tv*HIDv];
__device__ __align__(128) uint8_t g_sidx[(size_t)BH*Nv*Nv];   // 64MB logit-index bytes

// ---------------- PTX helpers ----------------
DEVFN uint32_t s2u(const void* p){
    uint32_t a;
    asm("{ .reg .u64 t; cvta.to.shared.u64 t, %1; cvt.u32.u64 %0, t; }" : "=r"(a) : "l"(p));
    return a;
}
DEVFN void cpasync16(uint32_t d, const void* s){
    asm volatile("cp.async.cg.shared.global [%0], [%1], 16;" :: "r"(d), "l"(s));
}
DEVFN void cpcommit(){ asm volatile("cp.async.commit_group;" ::: "memory"); }
template<int N> DEVFN void cpwait(){ asm volatile("cp.async.wait_group %0;" :: "n"(N) : "memory"); }
DEVFN void ldsm4(uint32_t* r, uint32_t addr){
    asm volatile("ldmatrix.sync.aligned.m8n8.x4.shared.b16 {%0,%1,%2,%3}, [%4];"
        : "=r"(r[0]), "=r"(r[1]), "=r"(r[2]), "=r"(r[3]) : "r"(addr));
}
DEVFN void ldsm4t(uint32_t* r, uint32_t addr){
    asm volatile("ldmatrix.sync.aligned.m8n8.x4.trans.shared.b16 {%0,%1,%2,%3}, [%4];"
        : "=r"(r[0]), "=r"(r[1]), "=r"(r[2]), "=r"(r[3]) : "r"(addr));
}
DEVFN void mma16816(float* c, const uint32_t* a, const uint32_t* b){
    asm volatile("mma.sync.aligned.m16n8k16.row.col.f32.bf16.bf16.f32 "
        "{%0,%1,%2,%3}, {%4,%5,%6,%7}, {%8,%9}, {%0,%1,%2,%3};"
        : "+f"(c[0]), "+f"(c[1]), "+f"(c[2]), "+f"(c[3])
        : "r"(a[0]), "r"(a[1]), "r"(a[2]), "r"(a[3]), "r"(b[0]), "r"(b[1]));
}
DEVFN void st_bf2(bf16* p, float a, float b){
    __nv_bfloat162 t = __halves2bfloat162(__float2bfloat16(a), __float2bfloat16(b));
    *reinterpret_cast<__nv_bfloat162*>(p) = t;
}
DEVFN uint32_t bf2pack(float hi, float lo){   // {lo, hi<<16} as bf16x2
    uint32_t r;
    asm("cvt.rn.bf16x2.f32 %0, %1, %2;" : "=r"(r) : "f"(hi), "f"(lo));
    return r;
}
DEVFN uint32_t swz(uint32_t r, uint32_t c16){ return (r<<7) + ((c16 ^ (r&7))<<4); }
DEVFN int clamp255(float f){ int i = __float2int_rn(f); return min(255, max(0, i)); }

// ---------------- epilogue functors ----------------
struct EpiQKV {
    bf16* q; bf16* k; bf16* v;
    DEVFN void operator()(int row, int col, float v0, float v1) const {
        int b=row>>10, n=row&1023;
        int sel=col>>10, rem=col&1023, h=rem>>6, d=rem&63;
        bf16* dst = (sel==0 ? q : (sel==1 ? k : v)) + (((long)(b*Hv+h))*Nv + n)*Dv + d;
        float sc = (sel==0) ? 2.0f : 1.0f;      // Q pre-scaled x2 (exact in bf16)
        st_bf2(dst, qz4(v0)*sc, qz4(v1)*sc);
    }
};
struct EpiProj {
    const float* x; const float* pb; const float* aw2; const float* ab2;
    float* x1; bf16* h2;
    DEVFN void operator()(int row, int col, float v0, float v1) const {
        float a = qz4(aw2[0]), bb = qz4(ab2[0]);
        float2 xv = *(const float2*)(x + (long)row*Cv + col);
        float2 pv = *(const float2*)(pb + col);
        float y0 = v0 + qz7(pv.x),  y1 = v1 + qz7(pv.y);
        float o0 = qz4(xv.x) + qz4(y0), o1 = qz4(xv.y) + qz4(y1);
        *(float2*)(x1 + (long)row*Cv + col) = make_float2(o0, o1);
        float h0 = qz4(qz4(qz4(o0)*a) + bb);
        float h1 = qz4(qz4(qz4(o1)*a) + bb);
        st_bf2(h2 + (long)row*Cv + col, h0, h1);
    }
};
struct EpiFc1 {
    const float* b1; bf16* m;
    DEVFN void operator()(int row, int col, float v0, float v1) const {
        float2 bv = *(const float2*)(b1 + col);
        float y0 = fmaxf(v0 + qz7(bv.x), 0.f);
        float y1 = fmaxf(v1 + qz7(bv.y), 0.f);
        st_bf2(m + (long)row*HIDv + col, qz4(y0), qz4(y1));
    }
};
struct EpiFc2 {
    const float* b2; const float* x1; float* out;
    DEVFN void operator()(int row, int col, float v0, float v1) const {
        float2 bv = *(const float2*)(b2 + col);
        float2 xv = *(const float2*)(x1 + (long)row*Cv + col);
        float y0 = v0 + qz7(bv.x), y1 = v1 + qz7(bv.y);
        *(float2*)(out + (long)row*Cv + col) =
            make_float2(qz4(xv.x) + qz4(y0), qz4(xv.y) + qz4(y1));
    }
};

// ---------------- GEMM: C[128x128] = A @ B^T, BK=64, 3-stage, swizzled ----------------
constexpr int TILE = 128*128;        // 16 KB
constexpr int GSTG = 2*TILE;
constexpr int GSM  = 3*GSTG;         // 96 KB

template<class Epi>
__global__ void __launch_bounds__(256,2)
gemm_mma(const bf16* __restrict__ A, const bf16* __restrict__ Bm, int K, Epi epi)
{
    extern __shared__ char dsm[];
    uint32_t base = s2u(dsm);
    int tid = threadIdx.x, wid = tid>>5, lane = tid&31;
    int wm = wid & 3, wn = wid >> 2;
    int m0 = blockIdx.y*128, n0 = blockIdx.x*128;
    const bf16* Ab = A + (long)m0*K;
    const bf16* Bb = Bm + (long)n0*K;
    const int KC = K >> 6;

    auto load = [&](int ch, int st){
        uint32_t ab = base + st*GSTG, bb = ab + TILE;
        const bf16* Ac = Ab + ch*64;
        const bf16* Bc = Bb + ch*64;
        #pragma unroll
        for(int j=0;j<4;j++){
            int i = tid + j*256; int r = i>>3, c = i&7;
            cpasync16(ab + swz(r,c), Ac + (long)r*K + c*8);
            cpasync16(bb + swz(r,c), Bc + (long)r*K + c*8);
        }
        cpcommit();
    };

    float acc[2][8][4];
    #pragma unroll
    for(int im=0;im<2;im++)
        #pragma unroll
        for(int j=0;j<8;j++)
            #pragma unroll
            for(int u=0;u<4;u++) acc[im][j][u]=0.f;

    load(0,0);
    load(1,1);
    int t = lane>>3, lr = lane&7;
    int rAdd = (t&1)*8 + lr, cAdd = (t>>1)*8;

    for(int c=0;c<KC;c++){
        if (c+1 < KC) cpwait<1>(); else cpwait<0>();
        __syncthreads();
        if (c+2 < KC) load(c+2, (c+2)%3);
        uint32_t ab = base + (c%3)*GSTG, bb = ab + TILE;
        #pragma unroll
        for(int kk=0; kk<64; kk+=16){
            int ch = (kk + cAdd)>>3;
            uint32_t afr[2][4];
            #pragma unroll
            for(int im=0;im<2;im++){
                int row = wm*32 + im*16 + rAdd;
                ldsm4(afr[im], ab + (row<<7) + ((ch ^ (row&7))<<4));
            }
            #pragma unroll
            for(int g=0; g<4; g++){
                int row = wn*64 + g*16 + rAdd;
                uint32_t r4[4];
                ldsm4(r4, bb + (row<<7) + ((ch ^ (row&7))<<4));
                uint32_t b0[2]={r4[0],r4[2]}, b1[2]={r4[1],r4[3]};
                #pragma unroll
                for(int im=0;im<2;im++){
                    mma16816(acc[im][2*g],   afr[im], b0);
                    mma16816(acc[im][2*g+1], afr[im], b1);
                }
            }
        }
    }

    int row0 = m0 + wm*32 + (lane>>2);
    int col0 = n0 + wn*64 + (lane&3)*2;
    #pragma unroll
    for(int im=0;im<2;im++)
        #pragma unroll
        for(int j=0;j<8;j++){
            int r = row0 + im*16, cc = col0 + j*8;
            epi(r,   cc, acc[im][j][0], acc[im][j][1]);
            epi(r+8, cc, acc[im][j][2], acc[im][j][3]);
        }
}

// ---------------- fused attention v3 ----------------
// smem: [lutE 32K replicated f32][Q 16K][KV0 16K][KV1 16K] = 80KB -> 2 CTAs/SM.
// Logit-index bytes go to global scratch (L2-resident; same thread writes & reads).
// QK mma accumulator seeded with 128.0f (exact) -> index = F2I + 2 IMNMX.
constexpr int FA_Q   = 32768;
constexpr int FA_KV0 = FA_Q  + TILE;
constexpr int FA_KV1 = FA_KV0 + TILE;
constexpr int FA_SM  = FA_KV1 + TILE;       // 81920

__global__ void __launch_bounds__(256,2)
fattn_k(const bf16* __restrict__ q, const bf16* __restrict__ k,
        const bf16* __restrict__ v, bf16* __restrict__ z2, uint8_t* __restrict__ sidx)
{
    extern __shared__ char dsm[];
    float* lutE = (float*)dsm;
    uint32_t base = s2u(dsm);
    uint32_t qs = base + FA_Q;
    uint32_t kv[2] = {base+FA_KV0, base+FA_KV1};

    int tid = threadIdx.x, wid = tid>>5, lane = tid&31;
    int bh = blockIdx.y, b = bh>>4, h = bh&15;
    int q0 = blockIdx.x*128;
    const bf16* Qb = q + ((long)bh*Nv + q0)*Dv;
    const bf16* Kb = k + (long)bh*Nv*Dv;
    const bf16* Vb = v + (long)bh*Nv*Dv;
    uint8_t* sA = sidx + ((long)(bh*8 + blockIdx.x))*131072 + wid*2048 + lane*8;

    // build bank-replicated exp LUT: lutE[u*32 + lane] = exp((u-128)/16 - 127/16)
    {
        float ev = expf((float)(tid-128)*0.0625f - 7.9375f);
        #pragma unroll
        for(int j=0;j<32;j++){
            float vj = __shfl_sync(0xffffffffu, ev, j);
            lutE[(wid*32 + j)*32 + lane] = vj;      // lanes hit distinct banks
        }
    }
    const float* eb = lutE + lane;                  // eb[u*32] conflict-free

    #pragma unroll
    for(int j=0;j<4;j++){
        int i = tid + j*256; int r = i>>3, c = i&7;
        cpasync16(qs + swz(r,c), Qb + (long)r*Dv + c*8);
    }
    cpcommit();

    int t = lane>>3, lr = lane&7;
    int rAdd = (t&1)*8 + lr, cAdd = (t>>1)*8;

    auto loadT = [&](const bf16* src, int st){
        #pragma unroll
        for(int j=0;j<4;j++){
            int i = tid + j*256; int r = i>>3, cc = i&7;
            cpasync16(kv[st] + swz(r,cc), src + (long)r*Dv + cc*8);
        }
        cpcommit();
    };

    loadT(Kb, 0);
    cpwait<0>(); __syncthreads();     // Q + K0 + LUT visible

    uint32_t qf[4][4];
    #pragma unroll
    for(int kk=0;kk<4;kk++){
        int row = wid*16 + rAdd;
        int ch = (kk*16 + cAdd)>>3;
        ldsm4(qf[kk], qs + (row<<7) + ((ch ^ (row&7))<<4));
    }

    auto computeS2 = [&](uint32_t kb_, int kg, float s2[2][4]){
        #pragma unroll
        for(int u=0;u<4;u++){ s2[0][u]=128.0f; s2[1][u]=128.0f; }   // seed: idx bias
        #pragma unroll
        for(int kk=0;kk<4;kk++){
            int row = kg*16 + rAdd;
            int ch = (kk*16 + cAdd)>>3;
            uint32_t r4[4];
            ldsm4(r4, kb_ + (row<<7) + ((ch ^ (row&7))<<4));
            uint32_t b0[2]={r4[0],r4[2]}, b1[2]={r4[1],r4[3]};
            mma16816(s2[0], qf[kk], b0);
            mma16816(s2[1], qf[kk], b1);
        }
    };

    // ---- pass A: S once, store index bytes to global, accumulate row sums ----
    float rs0 = 0.f, rs1 = 0.f;
    for(int c=0;c<8;c++){
        cpwait<0>(); __syncthreads();
        if (c<7) loadT(Kb + (long)((c+1)*128)*Dv, (c+1)&1);
        #pragma unroll
        for(int kg=0;kg<8;kg++){
            float s2[2][4];
            computeS2(kv[c&1], kg, s2);
            int u00=clamp255(s2[0][0]), u01=clamp255(s2[0][1]), u02=clamp255(s2[0][2]), u03=clamp255(s2[0][3]);
            int u10=clamp255(s2[1][0]), u11=clamp255(s2[1][1]), u12=clamp255(s2[1][2]), u13=clamp255(s2[1][3]);
            rs0 += eb[u00*32] + eb[u01*32] + eb[u10*32] + eb[u11*32];
            rs1 += eb[u02*32] + eb[u03*32] + eb[u12*32] + eb[u13*32];
            uint32_t w0 = (uint32_t)u00 | ((uint32_t)u01<<8) | ((uint32_t)u10<<16) | ((uint32_t)u11<<24);
            uint32_t w1 = (uint32_t)u02 | ((uint32_t)u03<<8) | ((uint32_t)u12<<16) | ((uint32_t)u13<<24);
            *reinterpret_cast<uint2*>(sA + c*16384 + kg*256) = make_uint2(w0, w1);
        }
    }
    rs0 += __shfl_xor_sync(0xffffffffu, rs0, 1);
    rs0 += __shfl_xor_sync(0xffffffffu, rs0, 2);
    rs1 += __shfl_xor_sync(0xffffffffu, rs1, 1);
    rs1 += __shfl_xor_sync(0xffffffffu, rs1, 2);
    float iv0 = 128.0f/rs0, iv1 = 128.0f/rs1;

    auto P = [&](uint32_t byte, float iv)->float{          // qz7(p) as float, p>=0
        float e = eb[byte*32];
        return fminf(rintf(e*iv), 127.f) * 0.0078125f;
    };

    // ---- pass B: P from stored bytes, O += P @ V ----
    float oacc[8][4];
    #pragma unroll
    for(int j=0;j<8;j++){ oacc[j][0]=0.f; oacc[j][1]=0.f; oacc[j][2]=0.f; oacc[j][3]=0.f; }

    loadT(Vb, 0);
    for(int c=0;c<8;c++){
        uint2 w[8];
        #pragma unroll
        for(int kg=0;kg<8;kg++)
            w[kg] = *reinterpret_cast<const uint2*>(sA + c*16384 + kg*256);
        cpwait<0>(); __syncthreads();
        if (c<7) loadT(Vb + (long)((c+1)*128)*Dv, (c+1)&1);
        #pragma unroll
        for(int kg=0;kg<8;kg++){
            uint32_t w0 = w[kg].x, w1 = w[kg].y;
            uint32_t pa[4];
            pa[0] = bf2pack(P((w0>>8)&255u, iv0), P(w0&255u, iv0));
            pa[1] = bf2pack(P((w1>>8)&255u, iv1), P(w1&255u, iv1));
            pa[2] = bf2pack(P(w0>>24, iv0),       P((w0>>16)&255u, iv0));
            pa[3] = bf2pack(P(w1>>24, iv1),       P((w1>>16)&255u, iv1));
            #pragma unroll
            for(int dg=0;dg<4;dg++){
                int row = kg*16 + rAdd;
                int ch = (dg*16 + cAdd)>>3;
                uint32_t r4[4];
                ldsm4t(r4, kv[c&1] + (row<<7) + ((ch ^ (row&7))<<4));
                uint32_t b0[2]={r4[0],r4[1]}, b1[2]={r4[2],r4[3]};
                mma16816(oacc[2*dg],   pa, b0);
                mma16816(oacc[2*dg+1], pa, b1);
            }
        }
    }

    int n = q0 + wid*16 + (lane>>2);
    long ro = ((long)(b*Nv) + n)*Cv + h*Dv;
    int d0 = 2*(lane&3);
    #pragma unroll
    for(int og=0;og<8;og++){
        st_bf2(z2 + ro +        og*8 + d0, qz4(oacc[og][0]), qz4(oacc[og][1]));
        st_bf2(z2 + ro + 8*Cv + og*8 + d0, qz4(oacc[og][2]), qz4(oacc[og][3]));
    }
}

// ---------------- prep: weight quant (5 tensors) + affine1, one launch ----------------
__global__ void prep_all(const float4* qw, const float4* kvw, const float4* pw,
                         const float4* f1w, const float4* f2w, const float4* x,
                         const float* a1w, const float* a1b,
                         uint2* wqkv, uint2* wpr, uint2* wf1, uint2* wf2, uint2* h1)
{
    int bx = blockIdx.x;
    if (bx >= 12288){          // affine1 region: 4096 blocks
        int i = (bx-12288)*256 + threadIdx.x;
        float a = qz4(a1w[0]), b = qz4(a1b[0]);
        float4 v = x[i];
        float o[4] = {v.x,v.y,v.z,v.w};
        #pragma unroll
        for(int u=0;u<4;u++){ float t = qz4(o[u])*a; o[u] = qz4(qz4(t)+b); }
        __nv_bfloat162 lo = __halves2bfloat162(__float2bfloat16(o[0]), __float2bfloat16(o[1]));
        __nv_bfloat162 hi = __halves2bfloat162(__float2bfloat16(o[2]), __float2bfloat16(o[3]));
        h1[i] = make_uint2(*(uint32_t*)&lo, *(uint32_t*)&hi);
        return;
    }
    const float4* src; uint2* dst; int li;
    if      (bx < 1024){ src=qw;  dst=wqkv;          li=bx; }
    else if (bx < 3072){ src=kvw; dst=wqkv + 262144; li=bx-1024; }
    else if (bx < 4096){ src=pw;  dst=wpr;           li=bx-3072; }
    else if (bx < 8192){ src=f1w; dst=wf1;           li=bx-4096; }
    else               { src=f2w; dst=wf2;           li=bx-8192; }
    int i = li*256 + threadIdx.x;
    float4 v = src[i];
    __nv_bfloat162 lo = __halves2bfloat162(__float2bfloat16(qz7(v.x)), __float2bfloat16(qz7(v.y)));
    __nv_bfloat162 hi = __halves2bfloat162(__float2bfloat16(qz7(v.z)), __float2bfloat16(qz7(v.w)));
    dst[i] = make_uint2(*(uint32_t*)&lo, *(uint32_t*)&hi);
}

// ---------------- host launcher ----------------
extern "C" void kernel_launch(void* const* d_in, const int* in_sizes, int n_in,
                              void* d_out, int out_size)
{
    (void)in_sizes; (void)n_in; (void)out_size;
    const float* x   = (const float*)d_in[0];
    const float* qw  = (const float*)d_in[1];
    const float* kvw = (const float*)d_in[2];
    const float* pw  = (const float*)d_in[3];
    const float* pb  = (const float*)d_in[4];
    const float* f1w = (const float*)d_in[5];
    const float* f1b = (const float*)d_in[6];
    const float* f2w = (const float*)d_in[7];
    const float* f2b = (const float*)d_in[8];
    const float* a1w = (const float*)d_in[9];
    const float* a1b = (const float*)d_in[10];
    const float* a2w = (const float*)d_in[11];
    const float* a2b = (const float*)d_in[12];
    float* out = (float*)d_out;

    bf16 *wqkv,*wpr,*wf1,*wf2,*h1,*qb,*kb,*vb,*z2,*h2,*m;
    float *x1; uint8_t *sidx;
    cudaGetSymbolAddress((void**)&wqkv,g_wqkv);
    cudaGetSymbolAddress((void**)&wpr, g_wpr);
    cudaGetSymbolAddress((void**)&wf1, g_wf1);
    cudaGetSymbolAddress((void**)&wf2, g_wf2);
    cudaGetSymbolAddress((void**)&h1,  g_h1);
    cudaGetSymbolAddress((void**)&qb,  g_qb);
    cudaGetSymbolAddress((void**)&kb,  g_kb);
    cudaGetSymbolAddress((void**)&vb,  g_vb);
    cudaGetSymbolAddress((void**)&z2,  g_z2);
    cudaGetSymbolAddress((void**)&x1,  g_x1);
    cudaGetSymbolAddress((void**)&h2,  g_h2);
    cudaGetSymbolAddress((void**)&m,   g_m);
    cudaGetSymbolAddress((void**)&sidx,g_sidx);

    cudaFuncSetAttribute(gemm_mma<EpiQKV>, cudaFuncAttributeMaxDynamicSharedMemorySize, GSM);
    cudaFuncSetAttribute(gemm_mma<EpiProj>,cudaFuncAttributeMaxDynamicSharedMemorySize, GSM);
    cudaFuncSetAttribute(gemm_mma<EpiFc1>, cudaFuncAttributeMaxDynamicSharedMemorySize, GSM);
    cudaFuncSetAttribute(gemm_mma<EpiFc2>, cudaFuncAttributeMaxDynamicSharedMemorySize, GSM);
    cudaFuncSetAttribute(fattn_k,          cudaFuncAttributeMaxDynamicSharedMemorySize, FA_SM);

    // 1) weights quant + affine1 (one launch)
    prep_all<<<16384, 256>>>((const float4*)qw, (const float4*)kvw, (const float4*)pw,
                             (const float4*)f1w, (const float4*)f2w, (const float4*)x,
                             a1w, a1b,
                             (uint2*)wqkv, (uint2*)wpr, (uint2*)wf1, (uint2*)wf2, (uint2*)h1);

    // 2) fused qkv projection (Q pre-scaled x2)
    { EpiQKV e{qb,kb,vb};
      gemm_mma<EpiQKV><<<dim3(3*Cv/128, Tv/128), 256, GSM>>>(h1, wqkv, Cv, e); }

    // 3) fused attention -> z2
    fattn_k<<<dim3(Nv/128, BH), 256, FA_SM>>>(qb, kb, vb, z2, sidx);

    // 4) proj + add1 + affine2
    { EpiProj e{x, pb, a2w, a2b, x1, h2};
      gemm_mma<EpiProj><<<dim3(Cv/128,  Tv/128), 256, GSM>>>(z2, wpr, Cv, e); }
    // 5) fc1 + relu
    { EpiFc1 e{f1b, m};
      gemm_mma<EpiFc1><<<dim3(HIDv/128, Tv/128), 256, GSM>>>(h2, wf1, Cv, e); }
    // 6) fc2 + add2 -> out
    { EpiFc2 e{f2b, x1, out};
      gemm_mma<EpiFc2><<<dim3(Cv/128,  Tv/128), 256, GSM>>>(m, wf2, HIDv, e); }
}